// round 15
// baseline (speedup 1.0000x reference)
#include <cuda_runtime.h>
#include <cstdint>

#define B_      4
#define N_      2048
#define D_      512
#define H_      8
#define DH_     64
#define ROWS_   (B_ * N_)
#define W3_     1536
#define KEXP_   0.18033688011112042f   // 64^-0.5 * log2(e)
#define NT_     (N_ / 64)

// ---------------------------------------------------------------------------
// Scratch: K natural [bbh][n][d], V transposed [bbh][d][n], bf16 hi/lo planes.
// ---------------------------------------------------------------------------
#define PLANE_  (16 * 2048 * 64)
__device__ unsigned short g_kh[PLANE_];
__device__ unsigned short g_kl[PLANE_];
__device__ unsigned short g_vh[PLANE_];
__device__ unsigned short g_vl[PLANE_];
__device__ float g_mu[ROWS_];
__device__ float g_rstd[ROWS_];

// ---------------------------------------------------------------------------
// helpers
// ---------------------------------------------------------------------------
__device__ __forceinline__ unsigned long long bcast2(float v) {
    unsigned long long r; unsigned int x = __float_as_uint(v);
    asm("mov.b64 %0, {%1, %2};" : "=l"(r) : "r"(x), "r"(x));
    return r;
}
__device__ __forceinline__ void ffma2(unsigned long long& d,
                                      unsigned long long a,
                                      unsigned long long b) {
    asm("fma.rn.f32x2 %0, %1, %2, %0;" : "+l"(d) : "l"(a), "l"(b));
}
union F2U { unsigned long long u; float2 f; };

__device__ __forceinline__ uint32_t pack_bf2(float lo_elem, float hi_elem) {
    uint32_t r;
    asm("cvt.rn.bf16x2.f32 %0, %1, %2;" : "=r"(r) : "f"(hi_elem), "f"(lo_elem));
    return r;   // low 16 bits = lo_elem
}
__device__ __forceinline__ float bf2lo(uint32_t p) { return __uint_as_float(p << 16); }
__device__ __forceinline__ float bf2hi(uint32_t p) { return __uint_as_float(p & 0xffff0000u); }
__device__ __forceinline__ void split2(float x0, float x1, uint32_t& hi, uint32_t& lo) {
    hi = pack_bf2(x0, x1);
    lo = pack_bf2(x0 - bf2lo(hi), x1 - bf2hi(hi));
}
__device__ __forceinline__ float ex2(float x) {
    float r; asm("ex2.approx.f32 %0, %1;" : "=f"(r) : "f"(x)); return r;
}

__device__ __forceinline__ void ldsm4(uint32_t addr, uint32_t& r0, uint32_t& r1,
                                      uint32_t& r2, uint32_t& r3) {
    asm volatile("ldmatrix.sync.aligned.m8n8.x4.shared.b16 {%0,%1,%2,%3}, [%4];"
                 : "=r"(r0), "=r"(r1), "=r"(r2), "=r"(r3) : "r"(addr));
}
__device__ __forceinline__ void mma_bf16(float& c0, float& c1, float& c2, float& c3,
                                         uint32_t a0, uint32_t a1, uint32_t a2, uint32_t a3,
                                         uint32_t b0, uint32_t b1) {
    asm volatile("mma.sync.aligned.m16n8k16.row.col.f32.bf16.bf16.f32 "
                 "{%0,%1,%2,%3}, {%4,%5,%6,%7}, {%8,%9}, {%0,%1,%2,%3};"
                 : "+f"(c0), "+f"(c1), "+f"(c2), "+f"(c3)
                 : "r"(a0), "r"(a1), "r"(a2), "r"(a3), "r"(b0), "r"(b1));
}

__device__ __forceinline__ void cp16(uint32_t dst, const void* src) {
    asm volatile("cp.async.cg.shared.global [%0], [%1], 16;" :: "r"(dst), "l"(src));
}
__device__ __forceinline__ void cp_commit() {
    asm volatile("cp.async.commit_group;");
}
template <int NN>
__device__ __forceinline__ void cp_wait() {
    asm volatile("cp.async.wait_group %0;" :: "n"(NN) : "memory");
}

__global__ void __launch_bounds__(256, 1) zero_out_kernel(float4* o) {
    o[blockIdx.x * 256 + threadIdx.x] = make_float4(0.f, 0.f, 0.f, 0.f);
}

__global__ void __launch_bounds__(128, 1)
ln_stats_kernel(const float* __restrict__ x) {
    int row = blockIdx.x;
    float4 v = reinterpret_cast<const float4*>(x + (size_t)row * D_)[threadIdx.x];
    float s  = v.x + v.y + v.z + v.w;
    float s2 = v.x * v.x + v.y * v.y + v.z * v.z + v.w * v.w;
    #pragma unroll
    for (int off = 16; off > 0; off >>= 1) {
        s  += __shfl_xor_sync(0xffffffffu, s,  off);
        s2 += __shfl_xor_sync(0xffffffffu, s2, off);
    }
    __shared__ float sh[8];
    int w = threadIdx.x >> 5;
    if ((threadIdx.x & 31) == 0) { sh[w] = s; sh[w + 4] = s2; }
    __syncthreads();
    if (threadIdx.x == 0) {
        s  = sh[0] + sh[1] + sh[2] + sh[3];
        s2 = sh[4] + sh[5] + sh[6] + sh[7];
        float mu  = s * (1.0f / D_);
        float var = s2 * (1.0f / D_) - mu * mu;
        g_mu[row] = mu; g_rstd[row] = rsqrtf(var + 1e-5f);
    }
}

// --------------------------- KV projection (FFMA2 inner loop) --------------
#define BM 128
#define BN 128
#define BK 16

__global__ void __launch_bounds__(256, 1)
kvproj_kernel(const float* __restrict__ x, const float* __restrict__ gamma,
              const float* __restrict__ beta, const float* __restrict__ W,
              int half) {
    __shared__ float As[BK][BM];
    __shared__ float Bs[BK][BN];
    int tid = threadIdx.x;
    int tx = tid & 15, ty = tid >> 4;
    int m0 = half * (2 * N_) + blockIdx.y * BM;
    int n0 = D_ + blockIdx.x * BN;

    unsigned long long acc2[8][4];
    #pragma unroll
    for (int i = 0; i < 8; i++)
        #pragma unroll
        for (int jp = 0; jp < 4; jp++) acc2[i][jp] = 0ull;

    for (int kt = 0; kt < D_; kt += BK) {
        #pragma unroll
        for (int i = 0; i < 8; i++) {
            int e = tid + i * 256;
            int m = e >> 4, kk = e & 15;
            int row = m0 + m;
            float xv = x[(size_t)row * D_ + kt + kk];
            xv = (xv - g_mu[row]) * g_rstd[row] * gamma[kt + kk] + beta[kt + kk];
            As[kk][m] = xv;
        }
        #pragma unroll
        for (int i = 0; i < 8; i++) {
            int e = tid + i * 256;
            int kk = e >> 7, n = e & 127;
            Bs[kk][n] = W[(size_t)(kt + kk) * W3_ + n0 + n];
        }
        __syncthreads();
        #pragma unroll
        for (int k = 0; k < BK; k++) {
            float4 a0 = *(const float4*)&As[k][ty * 8];
            float4 a1 = *(const float4*)&As[k][ty * 8 + 4];
            ulonglong2 b01 = *(const ulonglong2*)&Bs[k][tx * 8];
            ulonglong2 b23 = *(const ulonglong2*)&Bs[k][tx * 8 + 4];
            float av[8] = {a0.x, a0.y, a0.z, a0.w, a1.x, a1.y, a1.z, a1.w};
            #pragma unroll
            for (int i = 0; i < 8; i++) {
                unsigned long long aa = bcast2(av[i]);
                ffma2(acc2[i][0], aa, b01.x); ffma2(acc2[i][1], aa, b01.y);
                ffma2(acc2[i][2], aa, b23.x); ffma2(acc2[i][3], aa, b23.y);
            }
        }
        __syncthreads();
    }

    float acc[8][8];
    #pragma unroll
    for (int i = 0; i < 8; i++)
        #pragma unroll
        for (int jp = 0; jp < 4; jp++) {
            F2U u; u.u = acc2[i][jp];
            acc[i][2 * jp] = u.f.x; acc[i][2 * jp + 1] = u.f.y;
        }

    int col_rel = (n0 - D_) + tx * 8;
    int kvsel = col_rel >> 9, within = col_rel & 511;
    int h = within >> 6, d0 = within & 63;
    int r0 = m0 + ty * 8;
    int bb = (r0 >> 11) & 1;
    int nb = r0 & (N_ - 1);
    int bbh = bb * H_ + h;
    if (kvsel == 0) {
        #pragma unroll
        for (int i = 0; i < 8; i++) {
            uint32_t hp[4], lp[4];
            #pragma unroll
            for (int jp = 0; jp < 4; jp++)
                split2(acc[i][2 * jp], acc[i][2 * jp + 1], hp[jp], lp[jp]);
            size_t kb = ((size_t)bbh * N_ + nb + i) * DH_ + d0;
            *(uint4*)&g_kh[kb] = make_uint4(hp[0], hp[1], hp[2], hp[3]);
            *(uint4*)&g_kl[kb] = make_uint4(lp[0], lp[1], lp[2], lp[3]);
        }
    } else {
        #pragma unroll
        for (int j = 0; j < 8; j++) {
            uint32_t hp[4], lp[4];
            #pragma unroll
            for (int ip = 0; ip < 4; ip++)
                split2(acc[2 * ip][j], acc[2 * ip + 1][j], hp[ip], lp[ip]);
            size_t vb = ((size_t)bbh * DH_ + d0 + j) * N_ + nb;
            *(uint4*)&g_vh[vb] = make_uint4(hp[0], hp[1], hp[2], hp[3]);
            *(uint4*)&g_vl[vb] = make_uint4(lp[0], lp[1], lp[2], lp[3]);
        }
    }
}

// ---------------------------------------------------------------------------
// Kernel D: fused Q-proj (FFMA2) + tensor-core attention (bf16x3, split
// accumulator chains) + tensor-core out-proj. smem layout = R14 (proven).
// ---------------------------------------------------------------------------
#define QSTB_   36864
#define BUFB_   36864
#define ATTN_SMEM (QSTB_ + 2 * BUFB_)   // 110592

__global__ void __launch_bounds__(256, 2)
attn_kernel(const float* __restrict__ x, const float* __restrict__ gamma,
            const float* __restrict__ beta, const float* __restrict__ w_qkv,
            const float* __restrict__ w_out, float* __restrict__ out,
            int half) {
    extern __shared__ char smc[];
    float* smf = (float*)smc;
    uint32_t smb = (uint32_t)__cvta_generic_to_shared(smc);

    int tid = threadIdx.x;
    int tx = tid & 7, ty = tid >> 3;
    int lane = tid & 31;
    int w = tid >> 5;
    int g = lane >> 2, tig = lane & 3;
    int bb = blockIdx.y >> 3, h = blockIdx.y & 7;
    int b  = half * 2 + bb;
    int i0 = blockIdx.x * 128;
    int bbh = bb * H_ + h;

    const unsigned short* kh = g_kh + (size_t)bbh * N_ * DH_;
    const unsigned short* kl = g_kl + (size_t)bbh * N_ * DH_;
    const unsigned short* vh = g_vh + (size_t)bbh * DH_ * N_;
    const unsigned short* vl = g_vl + (size_t)bbh * DH_ * N_;

    // ---- prefetch tile 0 into buffer 0 ----
    {
        uint32_t bufb = smb + QSTB_;
        #pragma unroll
        for (int c = 0; c < 2; c++) {
            int cid = tid + c * 256;
            int n = cid >> 3, c8 = (cid & 7) * 8;
            uint32_t so = (uint32_t)(n * 72 + c8) * 2;
            cp16(bufb + so,         kh + (size_t)n * DH_ + c8);
            cp16(bufb + 9216 + so,  kl + (size_t)n * DH_ + c8);
            cp16(bufb + 18432 + so, vh + (size_t)n * N_ + c8);
            cp16(bufb + 27648 + so, vl + (size_t)n * N_ + c8);
        }
        cp_commit();
    }

    // ---- Q-proj (FFMA2), staging in buf1 ----
    {
        float* xs = smf + (QSTB_ + BUFB_) / 4;   // [32][132]
        float* Ws = xs + 4224;                   // [32][64]
        unsigned long long qa2[4][4];
        #pragma unroll
        for (int i = 0; i < 4; i++)
            #pragma unroll
            for (int q = 0; q < 4; q++) qa2[i][q] = 0ull;

        for (int kt = 0; kt < D_; kt += 32) {
            #pragma unroll
            for (int it = 0; it < 16; it++) {
                int e = tid + it * 256;
                int i = e >> 5, k = e & 31;
                int row = b * N_ + i0 + i;
                float xv = x[(size_t)row * D_ + kt + k];
                xs[k * 132 + i] = (xv - g_mu[row]) * g_rstd[row] * gamma[kt + k]
                                  + beta[kt + k];
            }
            #pragma unroll
            for (int it = 0; it < 8; it++) {
                int e = tid + it * 256;
                int d = e & 63, k = e >> 6;
                Ws[k * 64 + d] = w_qkv[(size_t)(kt + k) * W3_ + h * DH_ + d];
            }
            __syncthreads();
            #pragma unroll
            for (int k = 0; k < 32; k++) {
                float4 aq = *(const float4*)&xs[k * 132 + ty * 4];
                ulonglong2 bL = *(const ulonglong2*)&Ws[k * 64 + tx * 4];
                ulonglong2 bH = *(const ulonglong2*)&Ws[k * 64 + 32 + tx * 4];
                unsigned long long a0 = bcast2(aq.x), a1 = bcast2(aq.y);
                unsigned long long a2 = bcast2(aq.z), a3 = bcast2(aq.w);
                ffma2(qa2[0][0], a0, bL.x); ffma2(qa2[0][1], a0, bL.y);
                ffma2(qa2[0][2], a0, bH.x); ffma2(qa2[0][3], a0, bH.y);
                ffma2(qa2[1][0], a1, bL.x); ffma2(qa2[1][1], a1, bL.y);
                ffma2(qa2[1][2], a1, bH.x); ffma2(qa2[1][3], a1, bH.y);
                ffma2(qa2[2][0], a2, bL.x); ffma2(qa2[2][1], a2, bL.y);
                ffma2(qa2[2][2], a2, bH.x); ffma2(qa2[2][3], a2, bH.y);
                ffma2(qa2[3][0], a3, bL.x); ffma2(qa2[3][1], a3, bL.y);
                ffma2(qa2[3][2], a3, bH.x); ffma2(qa2[3][3], a3, bH.y);
            }
            __syncthreads();
        }
        #pragma unroll
        for (int i = 0; i < 4; i++)
            #pragma unroll
            for (int q = 0; q < 4; q++) {
                F2U u; u.u = qa2[i][q];
                int d = ((q >> 1) ? 32 : 0) + tx * 4 + (q & 1) * 2;
                int row = ty * 4 + i;
                uint32_t hp, lp;
                split2(u.f.x, u.f.y, hp, lp);
                *(uint32_t*)(smc + (row * 72 + d) * 2)         = hp;
                *(uint32_t*)(smc + 18432 + (row * 72 + d) * 2) = lp;
            }
    }
    __syncthreads();

    // ---- prefetch tile 1 into buffer 1 ----
    {
        uint32_t bufb = smb + QSTB_ + BUFB_;
        #pragma unroll
        for (int c = 0; c < 2; c++) {
            int cid = tid + c * 256;
            int n = cid >> 3, c8 = (cid & 7) * 8;
            uint32_t so = (uint32_t)(n * 72 + c8) * 2;
            cp16(bufb + so,         kh + (size_t)(64 + n) * DH_ + c8);
            cp16(bufb + 9216 + so,  kl + (size_t)(64 + n) * DH_ + c8);
            cp16(bufb + 18432 + so, vh + (size_t)n * N_ + 64 + c8);
            cp16(bufb + 27648 + so, vl + (size_t)n * N_ + 64 + c8);
        }
        cp_commit();
    }

    // ---- load Q fragments ----
    uint32_t qh[4][4], ql[4][4];
    {
        uint32_t qrow = 16 * w + (lane & 15);
        uint32_t qcol = (lane >> 4) * 8;
        #pragma unroll
        for (int kk = 0; kk < 4; kk++) {
            uint32_t off = (qrow * 72 + 16 * kk + qcol) * 2;
            ldsm4(smb + off,          qh[kk][0], qh[kk][1], qh[kk][2], qh[kk][3]);
            ldsm4(smb + 18432 + off,  ql[kk][0], ql[kk][1], ql[kk][2], ql[kk][3]);
        }
    }

    uint32_t bn = (lane & 7) + ((lane & 16) ? 8 : 0);
    uint32_t bkof = (lane & 8) ? 8 : 0;

    float oc[8][4];
    #pragma unroll
    for (int dt = 0; dt < 8; dt++)
        #pragma unroll
        for (int q = 0; q < 4; q++) oc[dt][q] = 0.f;
    float lpg = 0.f, lpg8 = 0.f;

    for (int t = 0; t < NT_; t++) {
        if (t == NT_ - 1) cp_wait<0>(); else cp_wait<1>();
        __syncthreads();
        uint32_t bufb = smb + QSTB_ + (uint32_t)(t & 1) * BUFB_;
        uint32_t kbh = bufb, kbl = bufb + 9216;
        uint32_t vbh = bufb + 18432, vbl = bufb + 27648;

        #pragma unroll
        for (int hf = 0; hf < 2; hf++) {
            // S = Q K^T over 4 n-tiles, TWO accumulator chains per tile
            float sc[4][4], scx[4][4];
            #pragma unroll
            for (int nt = 0; nt < 4; nt++)
                #pragma unroll
                for (int q = 0; q < 4; q++) { sc[nt][q] = 0.f; scx[nt][q] = 0.f; }

            #pragma unroll
            for (int kk = 0; kk < 4; kk++) {
                #pragma unroll
                for (int ap = 0; ap < 2; ap++) {
                    uint32_t koff = ((32 * hf + 16 * ap + bn) * 72 + 16 * kk + bkof) * 2;
                    uint32_t h0, h1, h2, h3, l0, l1, l2, l3;
                    ldsm4(kbh + koff, h0, h1, h2, h3);
                    ldsm4(kbl + koff, l0, l1, l2, l3);
                    int n0t = 2 * ap, n1t = 2 * ap + 1;
                    // chain A (sc): hi*hi  (+ ql*kh on even kk for balance)
                    // chain B (scx): qh*kl (+ ql*kh on odd kk)
                    mma_bf16(sc[n0t][0], sc[n0t][1], sc[n0t][2], sc[n0t][3],
                             qh[kk][0], qh[kk][1], qh[kk][2], qh[kk][3], h0, h1);
                    mma_bf16(sc[n1t][0], sc[n1t][1], sc[n1t][2], sc[n1t][3],
                             qh[kk][0], qh[kk][1], qh[kk][2], qh[kk][3], h2, h3);
                    mma_bf16(scx[n0t][0], scx[n0t][1], scx[n0t][2], scx[n0t][3],
                             qh[kk][0], qh[kk][1], qh[kk][2], qh[kk][3], l0, l1);
                    mma_bf16(scx[n1t][0], scx[n1t][1], scx[n1t][2], scx[n1t][3],
                             qh[kk][0], qh[kk][1], qh[kk][2], qh[kk][3], l2, l3);
                    if ((kk & 1) == 0) {
                        mma_bf16(sc[n0t][0], sc[n0t][1], sc[n0t][2], sc[n0t][3],
                                 ql[kk][0], ql[kk][1], ql[kk][2], ql[kk][3], h0, h1);
                        mma_bf16(sc[n1t][0], sc[n1t][1], sc[n1t][2], sc[n1t][3],
                                 ql[kk][0], ql[kk][1], ql[kk][2], ql[kk][3], h2, h3);
                    } else {
                        mma_bf16(scx[n0t][0], scx[n0t][1], scx[n0t][2], scx[n0t][3],
                                 ql[kk][0], ql[kk][1], ql[kk][2], ql[kk][3], h0, h1);
                        mma_bf16(scx[n1t][0], scx[n1t][1], scx[n1t][2], scx[n1t][3],
                                 ql[kk][0], ql[kk][1], ql[kk][2], ql[kk][3], h2, h3);
                    }
                }
            }

            #pragma unroll
            for (int k2 = 0; k2 < 2; k2++) {
                uint32_t pa_h[4], pa_l[4];
                #pragma unroll
                for (int e = 0; e < 2; e++) {
                    int nt = 2 * k2 + e;
                    float p0 = ex2((sc[nt][0] + scx[nt][0]) * KEXP_);
                    float p1 = ex2((sc[nt][1] + scx[nt][1]) * KEXP_);
                    float p2 = ex2((sc[nt][2] + scx[nt][2]) * KEXP_);
                    float p3 = ex2((sc[nt][3] + scx[nt][3]) * KEXP_);
                    lpg  += p0 + p1;
                    lpg8 += p2 + p3;
                    uint32_t h01, l01, h23, l23;
                    split2(p0, p1, h01, l01);
                    split2(p2, p3, h23, l23);
                    pa_h[2 * e] = h01; pa_h[2 * e + 1] = h23;
                    pa_l[2 * e] = l01; pa_l[2 * e + 1] = l23;
                }
                // PV: interleave the two independent d-tile chains per site
                #pragma unroll
                for (int a = 0; a < 4; a++) {
                    uint32_t voff = ((16 * a + bn) * 72 + 32 * hf + 16 * k2 + bkof) * 2;
                    uint32_t h0, h1, h2, h3, l0, l1, l2, l3;
                    ldsm4(vbh + voff, h0, h1, h2, h3);
                    ldsm4(vbl + voff, l0, l1, l2, l3);
                    int d0t = 2 * a, d1t = 2 * a + 1;
                    mma_bf16(oc[d0t][0], oc[d0t][1], oc[d0t][2], oc[d0t][3],
                             pa_h[0], pa_h[1], pa_h[2], pa_h[3], h0, h1);
                    mma_bf16(oc[d1t][0], oc[d1t][1], oc[d1t][2], oc[d1t][3],
                             pa_h[0], pa_h[1], pa_h[2], pa_h[3], h2, h3);
                    mma_bf16(oc[d0t][0], oc[d0t][1], oc[d0t][2], oc[d0t][3],
                             pa_h[0], pa_h[1], pa_h[2], pa_h[3], l0, l1);
                    mma_bf16(oc[d1t][0], oc[d1t][1], oc[d1t][2], oc[d1t][3],
                             pa_h[0], pa_h[1], pa_h[2], pa_h[3], l2, l3);
                    mma_bf16(oc[d0t][0], oc[d0t][1], oc[d0t][2], oc[d0t][3],
                             pa_l[0], pa_l[1], pa_l[2], pa_l[3], h0, h1);
                    mma_bf16(oc[d1t][0], oc[d1t][1], oc[d1t][2], oc[d1t][3],
                             pa_l[0], pa_l[1], pa_l[2], pa_l[3], h2, h3);
                }
            }
        }
        __syncthreads();

        if (t + 2 < NT_) {
            int j0n = (t + 2) * 64;
            #pragma unroll
            for (int c = 0; c < 2; c++) {
                int cid = tid + c * 256;
                int n = cid >> 3, c8 = (cid & 7) * 8;
                uint32_t so = (uint32_t)(n * 72 + c8) * 2;
                cp16(bufb + so,         kh + (size_t)(j0n + n) * DH_ + c8);
                cp16(bufb + 9216 + so,  kl + (size_t)(j0n + n) * DH_ + c8);
                cp16(bufb + 18432 + so, vh + (size_t)n * N_ + j0n + c8);
                cp16(bufb + 27648 + so, vl + (size_t)n * N_ + j0n + c8);
            }
            cp_commit();
        }
    }

    // ---- finalize l ----
    lpg  += __shfl_xor_sync(0xffffffffu, lpg, 1);
    lpg  += __shfl_xor_sync(0xffffffffu, lpg, 2);
    lpg8 += __shfl_xor_sync(0xffffffffu, lpg8, 1);
    lpg8 += __shfl_xor_sync(0xffffffffu, lpg8, 2);
    float invg = 1.0f / lpg, invg8 = 1.0f / lpg8;

    // ---- ao A-frags from PV C-frags (proven repack) ----
    uint32_t ah[4][4], al[4][4];
    #pragma unroll
    for (int kk = 0; kk < 4; kk++) {
        split2(oc[2 * kk][0] * invg,      oc[2 * kk][1] * invg,      ah[kk][0], al[kk][0]);
        split2(oc[2 * kk][2] * invg8,     oc[2 * kk][3] * invg8,     ah[kk][1], al[kk][1]);
        split2(oc[2 * kk + 1][0] * invg,  oc[2 * kk + 1][1] * invg,  ah[kk][2], al[kk][2]);
        split2(oc[2 * kk + 1][2] * invg8, oc[2 * kk + 1][3] * invg8, ah[kk][3], al[kk][3]);
    }

    // ---- out-proj: tensor bf16x3 (unchanged from R14) ----
    uint32_t wth = smb + QSTB_;
    uint32_t wtl = wth + 9216;
    int row0 = b * N_ + i0 + 16 * w + g;

    for (int nt = 0; nt < D_; nt += 64) {
        __syncthreads();
        #pragma unroll
        for (int it = 0; it < 8; it++) {
            int e = tid + it * 256;
            int n = e >> 5, d2 = (e & 31) * 2;
            float v0 = w_out[(size_t)(h * DH_ + d2) * D_ + nt + n];
            float v1 = w_out[(size_t)(h * DH_ + d2 + 1) * D_ + nt + n];
            uint32_t hp, lp; split2(v0, v1, hp, lp);
            *(uint32_t*)(smc + QSTB_ + (n * 72 + d2) * 2)        = hp;
            *(uint32_t*)(smc + QSTB_ + 9216 + (n * 72 + d2) * 2) = lp;
        }
        __syncthreads();

        float oc2[8][4];
        #pragma unroll
        for (int s = 0; s < 8; s++)
            #pragma unroll
            for (int q = 0; q < 4; q++) oc2[s][q] = 0.f;

        #pragma unroll
        for (int np = 0; np < 4; np++) {
            #pragma unroll
            for (int kk = 0; kk < 4; kk++) {
                uint32_t off = ((16 * np + bn) * 72 + 16 * kk + bkof) * 2;
                uint32_t h0, h1, h2, h3, l0, l1, l2, l3;
                ldsm4(wth + off, h0, h1, h2, h3);
                ldsm4(wtl + off, l0, l1, l2, l3);
                int s0 = 2 * np, s1 = 2 * np + 1;
                mma_bf16(oc2[s0][0], oc2[s0][1], oc2[s0][2], oc2[s0][3],
                         ah[kk][0], ah[kk][1], ah[kk][2], ah[kk][3], h0, h1);
                mma_bf16(oc2[s1][0], oc2[s1][1], oc2[s1][2], oc2[s1][3],
                         ah[kk][0], ah[kk][1], ah[kk][2], ah[kk][3], h2, h3);
                mma_bf16(oc2[s0][0], oc2[s0][1], oc2[s0][2], oc2[s0][3],
                         ah[kk][0], ah[kk][1], ah[kk][2], ah[kk][3], l0, l1);
                mma_bf16(oc2[s1][0], oc2[s1][1], oc2[s1][2], oc2[s1][3],
                         ah[kk][0], ah[kk][1], ah[kk][2], ah[kk][3], l2, l3);
                mma_bf16(oc2[s0][0], oc2[s0][1], oc2[s0][2], oc2[s0][3],
                         al[kk][0], al[kk][1], al[kk][2], al[kk][3], h0, h1);
                mma_bf16(oc2[s1][0], oc2[s1][1], oc2[s1][2], oc2[s1][3],
                         al[kk][0], al[kk][1], al[kk][2], al[kk][3], h2, h3);
            }
        }

        #pragma unroll
        for (int s = 0; s < 8; s++) {
            int nc = nt + 8 * s + 2 * tig;
            atomicAdd(&out[(size_t)row0 * D_ + nc],           oc2[s][0]);
            atomicAdd(&out[(size_t)row0 * D_ + nc + 1],       oc2[s][1]);
            atomicAdd(&out[(size_t)(row0 + 8) * D_ + nc],     oc2[s][2]);
            atomicAdd(&out[(size_t)(row0 + 8) * D_ + nc + 1], oc2[s][3]);
        }
    }
}

// ---------------------------------------------------------------------------
extern "C" void kernel_launch(void* const* d_in, const int* in_sizes, int n_in,
                              void* d_out, int out_size) {
    const float* x     = (const float*)d_in[0];
    const float* gamma = (const float*)d_in[1];
    const float* beta  = (const float*)d_in[2];
    const float* w_qkv = (const float*)d_in[3];
    const float* w_out = (const float*)d_in[4];
    float* out = (float*)d_out;
    (void)in_sizes; (void)n_in; (void)out_size;

    cudaFuncSetAttribute(attn_kernel,
                         cudaFuncAttributeMaxDynamicSharedMemorySize,
                         ATTN_SMEM);

    zero_out_kernel<<<ROWS_ * D_ / 1024, 256>>>((float4*)out);
    ln_stats_kernel<<<ROWS_, 128>>>(x);

    for (int half = 0; half < 2; half++) {
        kvproj_kernel<<<dim3(2 * D_ / BN, 2 * N_ / BM), 256>>>(
            x, gamma, beta, w_qkv, half);
        attn_kernel<<<dim3(N_ / 128, 2 * H_), 256, ATTN_SMEM>>>(
            x, gamma, beta, w_qkv, w_out, out, half);
    }
}